// round 2
// baseline (speedup 1.0000x reference)
#include <cuda_runtime.h>
#include <math.h>

// Problem constants
#define B 64
#define T 512
#define D 512
#define H 8
#define DH 64
#define BT (B*T)          // 32768
#define FF (4*D)          // 2048

// Scratch (allocation-free rule: __device__ globals)
__device__ float g_qin[BT*D];
__device__ float g_kin[BT*D];
__device__ float g_qp [BT*D];
__device__ float g_kp [BT*D];
__device__ float g_vp [BT*D];
__device__ float g_res[BT*D];
__device__ float g_hid[BT*FF];

// ---------------------------------------------------------------------------
// 1) q_in = queries + PE, k_in = keys + PE
//    PE: d<256 -> cos(t * invf[d]); d>=256 -> sin(t * invf[d-256])
//    invf[i] = 10000^(-2i/512) = exp(i * (-ln(10000)/256))
// ---------------------------------------------------------------------------
__global__ void add_pe_kernel(const float* __restrict__ q,
                              const float* __restrict__ k) {
    int idx = blockIdx.x * blockDim.x + threadIdx.x;
    if (idx >= BT * D) return;
    int d = idx % D;
    int t = (idx / D) % T;
    float pe;
    const float c = -logf(10000.0f) / (0.5f * (float)D);  // -ln(1e4)/256
    if (d < D/2) {
        float invf = expf((float)d * c);
        pe = cosf((float)t * invf);
    } else {
        float invf = expf((float)(d - D/2) * c);
        pe = sinf((float)t * invf);
    }
    g_qin[idx] = q[idx] + pe;
    g_kin[idx] = k[idx] + pe;
}

// ---------------------------------------------------------------------------
// 2) SGEMM: C[M,N] = A[M,K] * Bm[K,N], 128x128 tile, BK=8, 256 thr, 8x8/thread
//    MODE 0: store;  MODE 1: relu+store;  MODE 2: C += result (residual)
//    All shapes used are exact multiples of the tile -> no predication.
// ---------------------------------------------------------------------------
template<int MODE>
__global__ __launch_bounds__(256) void sgemm_kernel(
    const float* __restrict__ A, const float* __restrict__ Bm,
    float* __restrict__ C, int M, int N, int K)
{
    __shared__ float As[8][132];   // transposed A tile, padded (132: aligned + conflict-free)
    __shared__ float Bs[8][128];

    const int tid  = threadIdx.x;
    const int aRow = tid >> 1;            // 0..127
    const int aCol = (tid & 1) << 2;      // 0 or 4
    const int bRow = tid >> 5;            // 0..7
    const int bCol = (tid & 31) << 2;     // 0..124

    const float* Ag = A  + (blockIdx.y * 128 + aRow) * K + aCol;
    const float* Bg = Bm + bRow * N + blockIdx.x * 128 + bCol;

    const int ty = (tid >> 4) << 3;       // 0..120 (M dir)
    const int tx = (tid & 15) << 3;       // 0..120 (N dir)

    float acc[8][8];
#pragma unroll
    for (int i = 0; i < 8; i++)
#pragma unroll
        for (int j = 0; j < 8; j++) acc[i][j] = 0.0f;

    for (int k0 = 0; k0 < K; k0 += 8) {
        float4 a4 = *(const float4*)(Ag + k0);
        float4 b4 = *(const float4*)(Bg + (size_t)k0 * N);
        As[aCol+0][aRow] = a4.x;
        As[aCol+1][aRow] = a4.y;
        As[aCol+2][aRow] = a4.z;
        As[aCol+3][aRow] = a4.w;
        *(float4*)&Bs[bRow][bCol] = b4;
        __syncthreads();
#pragma unroll
        for (int k = 0; k < 8; k++) {
            float4 a0 = *(const float4*)&As[k][ty];
            float4 a1 = *(const float4*)&As[k][ty+4];
            float4 b0 = *(const float4*)&Bs[k][tx];
            float4 b1 = *(const float4*)&Bs[k][tx+4];
            float ra[8] = {a0.x,a0.y,a0.z,a0.w,a1.x,a1.y,a1.z,a1.w};
            float rb[8] = {b0.x,b0.y,b0.z,b0.w,b1.x,b1.y,b1.z,b1.w};
#pragma unroll
            for (int i = 0; i < 8; i++)
#pragma unroll
                for (int j = 0; j < 8; j++)
                    acc[i][j] = fmaf(ra[i], rb[j], acc[i][j]);
        }
        __syncthreads();
    }

    float* Cb = C + (size_t)(blockIdx.y * 128 + ty) * N + blockIdx.x * 128 + tx;
#pragma unroll
    for (int i = 0; i < 8; i++) {
#pragma unroll
        for (int j = 0; j < 8; j += 4) {
            float* p = Cb + (size_t)i * N + j;
            float4 v = make_float4(acc[i][j], acc[i][j+1], acc[i][j+2], acc[i][j+3]);
            if (MODE == 1) {
                v.x = fmaxf(v.x, 0.f); v.y = fmaxf(v.y, 0.f);
                v.z = fmaxf(v.z, 0.f); v.w = fmaxf(v.w, 0.f);
            }
            if (MODE == 2) {
                float4 c0 = *(const float4*)p;
                v.x += c0.x; v.y += c0.y; v.z += c0.z; v.w += c0.w;
            }
            *(float4*)p = v;
        }
    }
}

// ---------------------------------------------------------------------------
// 3) Fused attention per (b, h, 8 q-rows):
//    scores = qp . kp / 8, key-mask, softmax, q-mask, out = attn @ vp,
//    then residual add of q_in -> g_res
//    Block: 256 threads = 8 warps; warp w owns query row t = bx*8 + w.
// ---------------------------------------------------------------------------
__global__ __launch_bounds__(256) void attn_kernel(
    const int* __restrict__ qlens, const int* __restrict__ klens)
{
    __shared__ float sK[64][65];    // K chunk, pad 65 -> conflict-free column reads
    __shared__ float sA[8][512];    // attention probs per warp

    const int b = blockIdx.z, h = blockIdx.y;
    const int tid = threadIdx.x;
    const int w = tid >> 5, lane = tid & 31;
    const int t = blockIdx.x * 8 + w;
    const int klen = klens[b];
    const int qlen = qlens[b];

    // q row in registers (broadcast loads, L1-served)
    float qr[DH];
    const float* qrow = g_qp + ((size_t)(b*T + t)*H + h) * DH;
#pragma unroll
    for (int d = 0; d < DH; d++) qr[d] = qrow[d];

    float sc[16];
    for (int c = 0; c < T; c += 64) {
        __syncthreads();
        // cooperative K chunk load: 64 rows x 64 dims
        {
            int r = tid >> 2;
            int cb = (tid & 3) << 4;
            const float* krow = g_kp + ((size_t)(b*T + c + r)*H + h) * DH + cb;
            float4 k0 = *(const float4*)(krow);
            float4 k1 = *(const float4*)(krow + 4);
            float4 k2 = *(const float4*)(krow + 8);
            float4 k3 = *(const float4*)(krow + 12);
            sK[r][cb+ 0]=k0.x; sK[r][cb+ 1]=k0.y; sK[r][cb+ 2]=k0.z; sK[r][cb+ 3]=k0.w;
            sK[r][cb+ 4]=k1.x; sK[r][cb+ 5]=k1.y; sK[r][cb+ 6]=k1.z; sK[r][cb+ 7]=k1.w;
            sK[r][cb+ 8]=k2.x; sK[r][cb+ 9]=k2.y; sK[r][cb+10]=k2.z; sK[r][cb+11]=k2.w;
            sK[r][cb+12]=k3.x; sK[r][cb+13]=k3.y; sK[r][cb+14]=k3.z; sK[r][cb+15]=k3.w;
        }
        __syncthreads();
#pragma unroll
        for (int u = 0; u < 2; u++) {
            int kk = lane + u * 32;
            float s = 0.0f;
#pragma unroll
            for (int d = 0; d < DH; d++) s = fmaf(qr[d], sK[kk][d], s);
            sc[(c >> 5) + u] = s * 0.125f;   // 1/sqrt(64)
        }
    }

    // softmax over 512 keys (16 slots per lane), masked by klen
    float m = -3.4e38f;
#pragma unroll
    for (int slot = 0; slot < 16; slot++) {
        int j = slot * 32 + lane;
        if (j < klen) m = fmaxf(m, sc[slot]);
    }
#pragma unroll
    for (int off = 16; off; off >>= 1) m = fmaxf(m, __shfl_xor_sync(0xffffffffu, m, off));

    float sum = 0.0f;
    float p[16];
#pragma unroll
    for (int slot = 0; slot < 16; slot++) {
        int j = slot * 32 + lane;
        p[slot] = (j < klen) ? expf(sc[slot] - m) : 0.0f;
        sum += p[slot];
    }
#pragma unroll
    for (int off = 16; off; off >>= 1) sum += __shfl_xor_sync(0xffffffffu, sum, off);
    float inv = 1.0f / sum;

#pragma unroll
    for (int slot = 0; slot < 16; slot++) sA[w][slot * 32 + lane] = p[slot] * inv;
    __syncwarp();

    // out = attn @ V  (each lane accumulates 2 head dims), q-mask via skip
    float acc0 = 0.0f, acc1 = 0.0f;
    const int d0 = lane * 2;
    if (t < qlen) {
        const float* vbase = g_vp + ((size_t)(b*T)*H + h) * DH + d0;
        for (int s = 0; s < klen; s++) {
            float a = sA[w][s];
            float2 v = *(const float2*)(vbase + (size_t)s * (H * DH));
            acc0 = fmaf(a, v.x, acc0);
            acc1 = fmaf(a, v.y, acc1);
        }
    }
    // residual: + q_in (PE-augmented queries)
    const float* qi = g_qin + (size_t)(b*T + t) * D + h * DH + d0;
    float*       ro = g_res + (size_t)(b*T + t) * D + h * DH + d0;
    ro[0] = acc0 + qi[0];
    ro[1] = acc1 + qi[1];
}

// ---------------------------------------------------------------------------
// 4) Mean over T: out[b, d] = mean_t g_res[b, t, d]
// ---------------------------------------------------------------------------
__global__ void mean_kernel(float* __restrict__ out) {
    int b = blockIdx.x;
    int d = threadIdx.x;
    float s = 0.0f;
    const float* base = g_res + (size_t)b * T * D + d;
    for (int t = 0; t < T; t++) s += base[(size_t)t * D];
    out[b * D + d] = s * (1.0f / (float)T);
}

// ---------------------------------------------------------------------------
extern "C" void kernel_launch(void* const* d_in, const int* in_sizes, int n_in,
                              void* d_out, int out_size) {
    const float* queries = (const float*)d_in[0];
    const float* keys    = (const float*)d_in[1];
    const int*   qlens   = (const int*)  d_in[2];
    const int*   klens   = (const int*)  d_in[3];
    const float* W_Q     = (const float*)d_in[4];
    const float* W_K     = (const float*)d_in[5];
    const float* W_V     = (const float*)d_in[6];
    const float* fw1     = (const float*)d_in[7];
    const float* fw2     = (const float*)d_in[8];
    float* out = (float*)d_out;

    float *qin, *kin, *qp, *kp, *vp, *res, *hid;
    cudaGetSymbolAddress((void**)&qin, g_qin);
    cudaGetSymbolAddress((void**)&kin, g_kin);
    cudaGetSymbolAddress((void**)&qp,  g_qp);
    cudaGetSymbolAddress((void**)&kp,  g_kp);
    cudaGetSymbolAddress((void**)&vp,  g_vp);
    cudaGetSymbolAddress((void**)&res, g_res);
    cudaGetSymbolAddress((void**)&hid, g_hid);

    // 1) PE add
    {
        int n = BT * D;
        add_pe_kernel<<<(n + 255) / 256, 256>>>(queries, keys);
    }
    // 2) projections: qp = qin*W_Q, kp = kin*W_K, vp = kp*W_V
    {
        dim3 grid(D / 128, BT / 128);
        sgemm_kernel<0><<<grid, 256>>>(qin, W_Q, qp, BT, D, D);
        sgemm_kernel<0><<<grid, 256>>>(kin, W_K, kp, BT, D, D);
        sgemm_kernel<0><<<grid, 256>>>(kp,  W_V, vp, BT, D, D);
    }
    // 3) attention + residual -> res
    {
        dim3 grid(T / 8, H, B);
        attn_kernel<<<grid, 256>>>(qlens, klens);
    }
    // 4) FFN: hid = relu(res*fw1); res += hid*fw2
    {
        dim3 g1(FF / 128, BT / 128);
        sgemm_kernel<1><<<g1, 256>>>(res, fw1, hid, BT, FF, D);
        dim3 g2(D / 128, BT / 128);
        sgemm_kernel<2><<<g2, 256>>>(hid, fw2, res, BT, D, FF);
    }
    // 5) mean over T
    mean_kernel<<<B, D>>>(out);
}

// round 3
// speedup vs baseline: 1.8089x; 1.8089x over previous
#include <cuda_runtime.h>
#include <math.h>

// Problem constants
#define B 64
#define T 512
#define D 512
#define H 8
#define DH 64
#define BT (B*T)          // 32768
#define FF (4*D)          // 2048

// Scratch (allocation-free rule: __device__ globals)
__device__ float g_qin[BT*D];
__device__ float g_kin[BT*D];
__device__ float g_qp [BT*D];
__device__ float g_kp [BT*D];
__device__ float g_vp [BT*D];
__device__ float g_res[BT*D];
__device__ float g_hid[BT*FF];

// ---------------------------------------------------------------------------
// tf32 helpers
// ---------------------------------------------------------------------------
__device__ __forceinline__ float f2tf(float x) {
    unsigned y;
    asm("cvt.rna.tf32.f32 %0, %1;" : "=r"(y) : "f"(x));
    return __uint_as_float(y);
}
__device__ __forceinline__ float4 cvt4(float4 v) {
    return make_float4(f2tf(v.x), f2tf(v.y), f2tf(v.z), f2tf(v.w));
}
__device__ __forceinline__ void mma_tf32(float* d, const unsigned* a, const unsigned* b) {
    asm volatile(
        "mma.sync.aligned.m16n8k8.row.col.f32.tf32.tf32.f32 "
        "{%0,%1,%2,%3}, {%4,%5,%6,%7}, {%8,%9}, {%0,%1,%2,%3};"
        : "+f"(d[0]), "+f"(d[1]), "+f"(d[2]), "+f"(d[3])
        : "r"(a[0]), "r"(a[1]), "r"(a[2]), "r"(a[3]), "r"(b[0]), "r"(b[1]));
}

// ---------------------------------------------------------------------------
// 1) q_in = queries + PE, k_in = keys + PE
// ---------------------------------------------------------------------------
__global__ void add_pe_kernel(const float* __restrict__ q,
                              const float* __restrict__ k) {
    int idx = blockIdx.x * blockDim.x + threadIdx.x;
    if (idx >= BT * D) return;
    int d = idx % D;
    int t = (idx / D) % T;
    float pe;
    const float c = -logf(10000.0f) / (0.5f * (float)D);  // -ln(1e4)/256
    if (d < D/2) {
        float invf = expf((float)d * c);
        pe = cosf((float)t * invf);
    } else {
        float invf = expf((float)(d - D/2) * c);
        pe = sinf((float)t * invf);
    }
    g_qin[idx] = q[idx] + pe;
    g_kin[idx] = k[idx] + pe;
}

// ---------------------------------------------------------------------------
// 2) Tensor-core GEMM (tf32 mma.sync): C[M,N] = A[M,K] * Bm[K,N]
//    128x128 block tile, BK=16, 8 warps (4x2), warp tile 32x64.
//    MODE 0: store;  MODE 1: relu+store;  MODE 2: C += result
//    All shapes are exact tile multiples -> no predication.
//    Smem pads: A [128][20] (bank = 20r+c, conflict-free frag loads),
//               B [16][136] (bank = 8c+r, conflict-free frag loads).
// ---------------------------------------------------------------------------
template<int MODE>
__global__ __launch_bounds__(256, 2) void mma_gemm(
    const float* __restrict__ A, const float* __restrict__ Bm,
    float* __restrict__ C, int M, int N, int K)
{
    __shared__ float As[2][128][20];
    __shared__ float Bs[2][16][136];

    const int tid  = threadIdx.x;
    const int lane = tid & 31;
    const int warp = tid >> 5;
    const int wm = (warp >> 1) << 5;   // 0,32,64,96
    const int wn = (warp & 1) << 6;    // 0,64
    const int r = lane >> 2;           // groupID (0..7)
    const int c = lane & 3;            // thread-in-group (0..3)

    // staging indices
    const int aRow = tid >> 2;         // 0..63
    const int aCol = (tid & 3) << 2;   // 0,4,8,12
    const int bRow = tid >> 5;         // 0..7
    const int bCol = (tid & 31) << 2;  // 0..124

    const float* Ag = A  + (size_t)(blockIdx.y * 128 + aRow) * K + aCol;
    const float* Bg = Bm + (size_t)bRow * N + blockIdx.x * 128 + bCol;

    float acc[2][8][4];
#pragma unroll
    for (int mf = 0; mf < 2; mf++)
#pragma unroll
        for (int nf = 0; nf < 8; nf++)
#pragma unroll
            for (int i = 0; i < 4; i++) acc[mf][nf][i] = 0.0f;

    // prologue: load + stage tile 0
    float4 av0 = *(const float4*)(Ag);
    float4 av1 = *(const float4*)(Ag + (size_t)64 * K);
    float4 bv0 = *(const float4*)(Bg);
    float4 bv1 = *(const float4*)(Bg + (size_t)8 * N);
    *(float4*)&As[0][aRow     ][aCol] = cvt4(av0);
    *(float4*)&As[0][aRow + 64][aCol] = cvt4(av1);
    *(float4*)&Bs[0][bRow     ][bCol] = cvt4(bv0);
    *(float4*)&Bs[0][bRow +  8][bCol] = cvt4(bv1);
    __syncthreads();

    int st = 0;
    for (int k0 = 16; ; k0 += 16) {
        const bool more = (k0 < K);
        if (more) {
            av0 = *(const float4*)(Ag + k0);
            av1 = *(const float4*)(Ag + (size_t)64 * K + k0);
            bv0 = *(const float4*)(Bg + (size_t)k0 * N);
            bv1 = *(const float4*)(Bg + (size_t)(k0 + 8) * N);
        }
        // compute on stage st
#pragma unroll
        for (int ks = 0; ks < 16; ks += 8) {
            unsigned af[2][4], bf[8][2];
#pragma unroll
            for (int mf = 0; mf < 2; mf++) {
                const int m0 = wm + mf * 16;
                af[mf][0] = __float_as_uint(As[st][m0 + r    ][ks + c    ]);
                af[mf][1] = __float_as_uint(As[st][m0 + r + 8][ks + c    ]);
                af[mf][2] = __float_as_uint(As[st][m0 + r    ][ks + c + 4]);
                af[mf][3] = __float_as_uint(As[st][m0 + r + 8][ks + c + 4]);
            }
#pragma unroll
            for (int nf = 0; nf < 8; nf++) {
                bf[nf][0] = __float_as_uint(Bs[st][ks + c    ][wn + nf * 8 + r]);
                bf[nf][1] = __float_as_uint(Bs[st][ks + c + 4][wn + nf * 8 + r]);
            }
#pragma unroll
            for (int mf = 0; mf < 2; mf++)
#pragma unroll
                for (int nf = 0; nf < 8; nf++)
                    mma_tf32(acc[mf][nf], af[mf], bf[nf]);
        }
        if (!more) break;
        const int ns = st ^ 1;
        *(float4*)&As[ns][aRow     ][aCol] = cvt4(av0);
        *(float4*)&As[ns][aRow + 64][aCol] = cvt4(av1);
        *(float4*)&Bs[ns][bRow     ][bCol] = cvt4(bv0);
        *(float4*)&Bs[ns][bRow +  8][bCol] = cvt4(bv1);
        __syncthreads();
        st = ns;
    }

    // epilogue
    float* Cbase = C + (size_t)(blockIdx.y * 128) * N + blockIdx.x * 128;
#pragma unroll
    for (int mf = 0; mf < 2; mf++) {
#pragma unroll
        for (int nf = 0; nf < 8; nf++) {
            const int row = wm + mf * 16 + r;
            const int col = wn + nf * 8 + c * 2;
            float* p0 = Cbase + (size_t)row * N + col;
            float* p1 = p0 + (size_t)8 * N;
            float2 v0 = make_float2(acc[mf][nf][0], acc[mf][nf][1]);
            float2 v1 = make_float2(acc[mf][nf][2], acc[mf][nf][3]);
            if (MODE == 1) {
                v0.x = fmaxf(v0.x, 0.f); v0.y = fmaxf(v0.y, 0.f);
                v1.x = fmaxf(v1.x, 0.f); v1.y = fmaxf(v1.y, 0.f);
            }
            if (MODE == 2) {
                float2 c0 = *(const float2*)p0;
                float2 c1 = *(const float2*)p1;
                v0.x += c0.x; v0.y += c0.y;
                v1.x += c1.x; v1.y += c1.y;
            }
            *(float2*)p0 = v0;
            *(float2*)p1 = v1;
        }
    }
}

// ---------------------------------------------------------------------------
// 3) Fused attention per (b, h, 8 q-rows) + residual add -> g_res
// ---------------------------------------------------------------------------
__global__ __launch_bounds__(256) void attn_kernel(
    const int* __restrict__ qlens, const int* __restrict__ klens)
{
    __shared__ float sK[64][65];
    __shared__ float sA[8][512];

    const int b = blockIdx.z, h = blockIdx.y;
    const int tid = threadIdx.x;
    const int w = tid >> 5, lane = tid & 31;
    const int t = blockIdx.x * 8 + w;
    const int klen = klens[b];
    const int qlen = qlens[b];

    float qr[DH];
    const float* qrow = g_qp + ((size_t)(b*T + t)*H + h) * DH;
#pragma unroll
    for (int d = 0; d < DH; d++) qr[d] = qrow[d];

    float sc[16];
    for (int c = 0; c < T; c += 64) {
        __syncthreads();
        {
            int rr = tid >> 2;
            int cb = (tid & 3) << 4;
            const float* krow = g_kp + ((size_t)(b*T + c + rr)*H + h) * DH + cb;
            float4 k0 = *(const float4*)(krow);
            float4 k1 = *(const float4*)(krow + 4);
            float4 k2 = *(const float4*)(krow + 8);
            float4 k3 = *(const float4*)(krow + 12);
            sK[rr][cb+ 0]=k0.x; sK[rr][cb+ 1]=k0.y; sK[rr][cb+ 2]=k0.z; sK[rr][cb+ 3]=k0.w;
            sK[rr][cb+ 4]=k1.x; sK[rr][cb+ 5]=k1.y; sK[rr][cb+ 6]=k1.z; sK[rr][cb+ 7]=k1.w;
            sK[rr][cb+ 8]=k2.x; sK[rr][cb+ 9]=k2.y; sK[rr][cb+10]=k2.z; sK[rr][cb+11]=k2.w;
            sK[rr][cb+12]=k3.x; sK[rr][cb+13]=k3.y; sK[rr][cb+14]=k3.z; sK[rr][cb+15]=k3.w;
        }
        __syncthreads();
#pragma unroll
        for (int u = 0; u < 2; u++) {
            int kk = lane + u * 32;
            float s = 0.0f;
#pragma unroll
            for (int d = 0; d < DH; d++) s = fmaf(qr[d], sK[kk][d], s);
            sc[(c >> 5) + u] = s * 0.125f;
        }
    }

    float m = -3.4e38f;
#pragma unroll
    for (int slot = 0; slot < 16; slot++) {
        int j = slot * 32 + lane;
        if (j < klen) m = fmaxf(m, sc[slot]);
    }
#pragma unroll
    for (int off = 16; off; off >>= 1) m = fmaxf(m, __shfl_xor_sync(0xffffffffu, m, off));

    float sum = 0.0f;
    float p[16];
#pragma unroll
    for (int slot = 0; slot < 16; slot++) {
        int j = slot * 32 + lane;
        p[slot] = (j < klen) ? expf(sc[slot] - m) : 0.0f;
        sum += p[slot];
    }
#pragma unroll
    for (int off = 16; off; off >>= 1) sum += __shfl_xor_sync(0xffffffffu, sum, off);
    float inv = 1.0f / sum;

#pragma unroll
    for (int slot = 0; slot < 16; slot++) sA[w][slot * 32 + lane] = p[slot] * inv;
    __syncwarp();

    float acc0 = 0.0f, acc1 = 0.0f;
    const int d0 = lane * 2;
    if (t < qlen) {
        const float* vbase = g_vp + ((size_t)(b*T)*H + h) * DH + d0;
        for (int s = 0; s < klen; s++) {
            float a = sA[w][s];
            float2 v = *(const float2*)(vbase + (size_t)s * (H * DH));
            acc0 = fmaf(a, v.x, acc0);
            acc1 = fmaf(a, v.y, acc1);
        }
    }
    const float* qi = g_qin + (size_t)(b*T + t) * D + h * DH + d0;
    float*       ro = g_res + (size_t)(b*T + t) * D + h * DH + d0;
    ro[0] = acc0 + qi[0];
    ro[1] = acc1 + qi[1];
}

// ---------------------------------------------------------------------------
// 4) Mean over T
// ---------------------------------------------------------------------------
__global__ void mean_kernel(float* __restrict__ out) {
    int b = blockIdx.x;
    int d = threadIdx.x;
    float s = 0.0f;
    const float* base = g_res + (size_t)b * T * D + d;
    for (int t = 0; t < T; t++) s += base[(size_t)t * D];
    out[b * D + d] = s * (1.0f / (float)T);
}

// ---------------------------------------------------------------------------
extern "C" void kernel_launch(void* const* d_in, const int* in_sizes, int n_in,
                              void* d_out, int out_size) {
    const float* queries = (const float*)d_in[0];
    const float* keys    = (const float*)d_in[1];
    const int*   qlens   = (const int*)  d_in[2];
    const int*   klens   = (const int*)  d_in[3];
    const float* W_Q     = (const float*)d_in[4];
    const float* W_K     = (const float*)d_in[5];
    const float* W_V     = (const float*)d_in[6];
    const float* fw1     = (const float*)d_in[7];
    const float* fw2     = (const float*)d_in[8];
    float* out = (float*)d_out;

    float *qin, *kin, *qp, *kp, *vp, *res, *hid;
    cudaGetSymbolAddress((void**)&qin, g_qin);
    cudaGetSymbolAddress((void**)&kin, g_kin);
    cudaGetSymbolAddress((void**)&qp,  g_qp);
    cudaGetSymbolAddress((void**)&kp,  g_kp);
    cudaGetSymbolAddress((void**)&vp,  g_vp);
    cudaGetSymbolAddress((void**)&res, g_res);
    cudaGetSymbolAddress((void**)&hid, g_hid);

    // 1) PE add
    {
        int n = BT * D;
        add_pe_kernel<<<(n + 255) / 256, 256>>>(queries, keys);
    }
    // 2) projections: qp = qin*W_Q, kp = kin*W_K, vp = kp*W_V
    {
        dim3 grid(D / 128, BT / 128);
        mma_gemm<0><<<grid, 256>>>(qin, W_Q, qp, BT, D, D);
        mma_gemm<0><<<grid, 256>>>(kin, W_K, kp, BT, D, D);
        mma_gemm<0><<<grid, 256>>>(kp,  W_V, vp, BT, D, D);
    }
    // 3) attention + residual -> res
    {
        dim3 grid(T / 8, H, B);
        attn_kernel<<<grid, 256>>>(qlens, klens);
    }
    // 4) FFN: hid = relu(res*fw1); res += hid*fw2
    {
        dim3 g1(FF / 128, BT / 128);
        mma_gemm<1><<<g1, 256>>>(res, fw1, hid, BT, FF, D);
        dim3 g2(D / 128, BT / 128);
        mma_gemm<2><<<g2, 256>>>(hid, fw2, res, BT, D, FF);
    }
    // 5) mean over T
    mean_kernel<<<B, D>>>(out);
}